// round 16
// baseline (speedup 1.0000x reference)
#include <cuda_runtime.h>
#include <cuda_bf16.h>
#include <math.h>
#include <stdint.h>

#define NP 2048
#define TT 1024
#define BB 16
#define JJ 64
#define BJ 1024
#define NSQ 7
#define NPOW 6

// MMA smem: 6 operand tiles [128 rows x 64 bf16] pitch 144B, double buffered
#define OPBYTES 18432u
#define BUFBYTES (6u * OPBYTES)        // 110592
#define SMEMSZ (2 * 110592 + 1024)     // 222208, 1 CTA/SM

// ================= PTX helpers =================
__device__ __forceinline__ uint32_t smem_to_u32(const void* p) {
    uint32_t a;
    asm("{ .reg .u64 t; cvta.to.shared.u64 t, %1; cvt.u32.u64 %0, t; }" : "=r"(a) : "l"(p));
    return a;
}
__device__ __forceinline__ void ldsm4(uint32_t* r, uint32_t addr) {
    asm volatile("ldmatrix.sync.aligned.m8n8.x4.shared.b16 {%0,%1,%2,%3}, [%4];"
                 : "=r"(r[0]), "=r"(r[1]), "=r"(r[2]), "=r"(r[3]) : "r"(addr));
}
__device__ __forceinline__ void mma_bf16(float* d, const uint32_t* a, uint32_t b0, uint32_t b1) {
    asm volatile(
        "mma.sync.aligned.m16n8k16.row.col.f32.bf16.bf16.f32 "
        "{%0,%1,%2,%3}, {%4,%5,%6,%7}, {%8,%9}, {%0,%1,%2,%3};"
        : "+f"(d[0]), "+f"(d[1]), "+f"(d[2]), "+f"(d[3])
        : "r"(a[0]), "r"(a[1]), "r"(a[2]), "r"(a[3]), "r"(b0), "r"(b1));
}
__device__ __forceinline__ void cpasync16(uint32_t dst, const void* src) {
    asm volatile("cp.async.cg.shared.global [%0], [%1], 16;" :: "r"(dst), "l"(src));
}
#define CP_COMMIT() asm volatile("cp.async.commit_group;" ::: "memory")
#define CP_WAIT0()  asm volatile("cp.async.wait_group 0;" ::: "memory")
#define CP_WAIT1()  asm volatile("cp.async.wait_group 1;" ::: "memory")

// ================= device scratch =================
__device__ __align__(16) float g_Dt  [NP*TT];
__device__ __align__(16) float g_DtD [NP*NP];
__device__ __align__(16) float g_DDt [TT*TT];
__device__ __align__(16) float g_B1  [TT*TT];
__device__ __align__(16) float g_B2  [TT*TT];
__device__ __align__(16) float g_DtY [NP*BJ];
__device__ __align__(16) float g_DtYT[BJ*NP];
__device__ __align__(16) float g_CcT [BJ*NP];
__device__ __align__(16) float g_CpT [BJ*NP];
__device__ __align__(16) float g_CnT [BJ*NP];
__device__ __align__(16) float g_lamT[BJ*NP];
__device__ __align__(16) __nv_bfloat16 g_Dh  [TT*NP], g_Dm  [TT*NP], g_Dl  [TT*NP];
__device__ __align__(16) __nv_bfloat16 g_B1h [TT*TT], g_B1m [TT*TT], g_B1l [TT*TT];
__device__ __align__(16) __nv_bfloat16 g_DtDh[NP*NP], g_DtDm[NP*NP], g_DtDl[NP*NP];
__device__ __align__(16) __nv_bfloat16 g_CpTh[BJ*NP], g_CpTm[BJ*NP], g_CpTl[BJ*NP];
__device__ float g_x[TT], g_y[TT];
__device__ float g_acc[16];
__device__ float g_L, g_t, g_tconst, g_norm2;
__device__ int   g_do, g_done, g_ctr;

// ================= small kernels =================
__global__ void k_init() {
    int idx = blockIdx.x * blockDim.x + threadIdx.x;
    int stride = gridDim.x * blockDim.x;
    __nv_bfloat16 z = __float2bfloat16(0.f);
    for (int i = idx; i < BJ*NP; i += stride) {
        g_CcT[i] = 0.f; g_CpT[i] = 0.f;
        g_CpTh[i] = z; g_CpTm[i] = z; g_CpTl[i] = z;
    }
    if (idx < TT) {
        unsigned h = (unsigned)idx * 2654435761u;
        g_x[idx] = 0.5f + (float)(h >> 20) * (1.0f / 4096.0f);
    }
    if (idx < 16) g_acc[idx] = 0.f;
    if (idx == 0) {
        g_t = 1.f; g_tconst = 0.f; g_norm2 = 0.f;
        g_do = 0; g_done = 0; g_L = 0.f; g_ctr = 0;
    }
}
__global__ void k_zero(int s) { g_acc[s] = 0.f; }
__global__ void k_phase_reset() { g_done = 0; g_norm2 = 0.f; }

__global__ void k_transpose(const float* __restrict__ D) {   // D[TT,NP] -> Dt[NP,TT]
    __shared__ float tile[32][33];
    int p0 = blockIdx.x * 32, t0 = blockIdx.y * 32;
    int tx = threadIdx.x, ty = threadIdx.y;
#pragma unroll
    for (int r = 0; r < 32; r += 8)
        tile[ty + r][tx] = D[(size_t)(t0 + ty + r) * NP + p0 + tx];
    __syncthreads();
#pragma unroll
    for (int r = 0; r < 32; r += 8)
        g_Dt[(size_t)(p0 + ty + r) * TT + t0 + tx] = tile[tx][ty + r];
}
__global__ void k_transposeG(const float* __restrict__ src, float* __restrict__ dst,
                             int R, int C) {
    __shared__ float tile[32][33];
    int c0 = blockIdx.x * 32, r0 = blockIdx.y * 32;
    int tx = threadIdx.x, ty = threadIdx.y;
#pragma unroll
    for (int r = 0; r < 32; r += 8)
        tile[ty + r][tx] = src[(size_t)(r0 + ty + r) * C + c0 + tx];
    __syncthreads();
#pragma unroll
    for (int r = 0; r < 32; r += 8)
        dst[(size_t)(c0 + ty + r) * R + r0 + tx] = tile[tx][ty + r];
}

__device__ __forceinline__ void split3(float v, __nv_bfloat16& h, __nv_bfloat16& m,
                                       __nv_bfloat16& l) {
    __nv_bfloat16 hb = __float2bfloat16(v);
    float r1 = v - __bfloat162float(hb);
    __nv_bfloat16 mb = __float2bfloat16(r1);
    float r2 = r1 - __bfloat162float(mb);
    h = hb; m = mb; l = __float2bfloat16(r2);
}
__global__ void k_split3(const float* __restrict__ src, __nv_bfloat16* __restrict__ h,
                         __nv_bfloat16* __restrict__ m, __nv_bfloat16* __restrict__ l, int n) {
    int idx = blockIdx.x * blockDim.x + threadIdx.x;
    int stride = gridDim.x * blockDim.x;
    for (int i = idx; i < n; i += stride) split3(src[i], h[i], m[i], l[i]);
}
__global__ void k_scale_split3(const float* __restrict__ src, float* __restrict__ dst,
                               __nv_bfloat16* __restrict__ h, __nv_bfloat16* __restrict__ m,
                               __nv_bfloat16* __restrict__ l, int n, int slot) {
    float inv = rsqrtf(g_acc[slot]);
    int idx = blockIdx.x * blockDim.x + threadIdx.x;
    int stride = gridDim.x * blockDim.x;
    for (int i = idx; i < n; i += stride) {
        float v = src[i] * inv;
        dst[i] = v;
        split3(v, h[i], m[i], l[i]);
    }
}

__global__ void k_fro(const float* __restrict__ A, int n, int slot) {
    __shared__ float red[256];
    float s = 0.f;
    for (int i = blockIdx.x * blockDim.x + threadIdx.x; i < n; i += gridDim.x * blockDim.x) {
        float v = A[i]; s += v * v;
    }
    red[threadIdx.x] = s; __syncthreads();
    for (int o = 128; o > 0; o >>= 1) {
        if (threadIdx.x < o) red[threadIdx.x] += red[threadIdx.x + o];
        __syncthreads();
    }
    if (threadIdx.x == 0) atomicAdd(&g_acc[slot], red[0]);
}
__global__ void k_matvec(const float* __restrict__ A, const float* __restrict__ xin,
                         float* __restrict__ yout, int slot, int mode) {
    int row  = blockIdx.x * 8 + (threadIdx.x >> 5);
    int lane = threadIdx.x & 31;
    const float* ar = A + (size_t)row * TT;
    float s = 0.f;
    for (int k = lane; k < TT; k += 32) s += ar[k] * xin[k];
#pragma unroll
    for (int o = 16; o > 0; o >>= 1) s += __shfl_down_sync(0xffffffffu, s, o);
    if (lane == 0) {
        yout[row] = s;
        if (mode == 0) atomicAdd(&g_acc[slot], s * s);
        else { float xv = xin[row]; atomicAdd(&g_acc[10], xv * s); atomicAdd(&g_acc[11], xv * xv); }
    }
}
__global__ void k_normalize(int slot) {
    int i = threadIdx.x;
    float inv = rsqrtf(g_acc[slot]);
    g_x[i] = g_y[i] * inv;
}
__global__ void k_setL() { g_L = g_acc[11] / g_acc[10]; }

__global__ void k_commit() {
    if (!g_do) return;
    float tc = g_tconst;
    int idx = blockIdx.x * blockDim.x + threadIdx.x;
    int stride = gridDim.x * blockDim.x;
    for (int i = idx; i < BJ*NP; i += stride) {
        float cn = g_CnT[i], cc = g_CcT[i];
        float cp = cn + tc * (cn - cc);
        g_CpT[i] = cp; g_CcT[i] = cn;
        split3(cp, g_CpTh[i], g_CpTm[i], g_CpTl[i]);
    }
}
__global__ void k_reweight() {
    __shared__ float red[256];
    int c = blockIdx.x;
    const float* row = g_CcT + (size_t)c * NP;
    float s = 0.f;
    for (int p = threadIdx.x; p < NP; p += 256) {
        float w = 1.f / (fabsf(row[p]) + 1e-10f);
        s += w * w;
    }
    red[threadIdx.x] = s; __syncthreads();
    for (int o = 128; o > 0; o >>= 1) {
        if (threadIdx.x < o) red[threadIdx.x] += red[threadIdx.x + o];
        __syncthreads();
    }
    float inv = rsqrtf(red[0]);
    for (int p = threadIdx.x; p < NP; p += 256) {
        float w = 1.f / (fabsf(row[p]) + 1e-10f);
        g_lamT[(size_t)c * NP + p] = 0.1f * 2048.f * w * inv;
    }
}
__global__ void k_output(float* __restrict__ out) {
    int idx = blockIdx.x * blockDim.x + threadIdx.x;
    int stride = gridDim.x * blockDim.x;
    for (int i = idx; i < BB * NP * JJ; i += stride) {
        int j = i & 63;
        int p = (i >> 6) & (NP - 1);
        int b = i >> 17;
        out[i] = g_CcT[(size_t)(b * JJ + j) * NP + p];
    }
}

// ============== fp32 SGEMM, 64x64 tile (unchanged; DtD/DDt-free path for sensitive GEMMs) =====
template<int BMAP, int EPI>
__global__ void __launch_bounds__(256) k_sgemm64(const float* __restrict__ A,
                                                 const float* __restrict__ B,
                                                 float* __restrict__ C,
                                                 int M, int N, int K, int slot)
{
    __shared__ float As[2][16][68];
    __shared__ float Bs[2][16][64];
    __shared__ float red[256];
    const int tid   = threadIdx.x;
    const int rowA0 = blockIdx.y * 64;
    const int colB0 = blockIdx.x * 64;
    const int aRow = tid >> 2,  aCol = (tid & 3) * 4;
    const int bRow = tid >> 4,  bCol = (tid & 15) * 4;
    const int tr = tid >> 4,    tc = tid & 15;
    const float* Ag = A + (size_t)(rowA0 + aRow) * K + aCol;

    float acc[4][4];
#pragma unroll
    for (int i = 0; i < 4; i++)
#pragma unroll
        for (int j = 0; j < 4; j++) acc[i][j] = 0.f;

    float4 a0, b0;
    {
        a0 = *reinterpret_cast<const float4*>(Ag);
        if (BMAP == 0) {
            b0 = *reinterpret_cast<const float4*>(B + (size_t)(bRow) * N + colB0 + bCol);
        } else {
            int c = colB0 + bCol;
            const float* Bb = B + (size_t)(c >> 6) * (TT * JJ) + (c & 63);
            b0 = *reinterpret_cast<const float4*>(Bb + (size_t)(bRow) * JJ);
        }
        As[0][aCol + 0][aRow] = a0.x; As[0][aCol + 1][aRow] = a0.y;
        As[0][aCol + 2][aRow] = a0.z; As[0][aCol + 3][aRow] = a0.w;
        *reinterpret_cast<float4*>(&Bs[0][bRow][bCol]) = b0;
    }
    __syncthreads();

    int buf = 0;
    for (int k0 = 16; k0 <= K; k0 += 16) {
        if (k0 < K) {
            a0 = *reinterpret_cast<const float4*>(Ag + k0);
            if (BMAP == 0) {
                b0 = *reinterpret_cast<const float4*>(B + (size_t)(k0 + bRow) * N + colB0 + bCol);
            } else {
                int c = colB0 + bCol;
                const float* Bb = B + (size_t)(c >> 6) * (TT * JJ) + (c & 63);
                b0 = *reinterpret_cast<const float4*>(Bb + (size_t)(k0 + bRow) * JJ);
            }
        }
#pragma unroll
        for (int kk = 0; kk < 16; kk++) {
            float4 m0 = *reinterpret_cast<const float4*>(&As[buf][kk][tr * 4]);
            float4 n0 = *reinterpret_cast<const float4*>(&Bs[buf][kk][tc * 4]);
            float rm[4] = {m0.x, m0.y, m0.z, m0.w};
            float rn[4] = {n0.x, n0.y, n0.z, n0.w};
#pragma unroll
            for (int i = 0; i < 4; i++)
#pragma unroll
                for (int j = 0; j < 4; j++) acc[i][j] += rm[i] * rn[j];
        }
        if (k0 < K) {
            int nb = buf ^ 1;
            As[nb][aCol + 0][aRow] = a0.x; As[nb][aCol + 1][aRow] = a0.y;
            As[nb][aCol + 2][aRow] = a0.z; As[nb][aCol + 3][aRow] = a0.w;
            *reinterpret_cast<float4*>(&Bs[nb][bRow][bCol]) = b0;
            __syncthreads();
            buf = nb;
        }
    }

    float loc = 0.f;
#pragma unroll
    for (int i = 0; i < 4; i++) {
        size_t base = (size_t)(rowA0 + tr * 4 + i) * N + colB0 + tc * 4;
        float4 r;
        r.x = acc[i][0]; r.y = acc[i][1]; r.z = acc[i][2]; r.w = acc[i][3];
        *reinterpret_cast<float4*>(&C[base]) = r;
        if (EPI == 1) loc += r.x * r.x + r.y * r.y + r.z * r.z + r.w * r.w;
    }
    if (EPI == 1) {
        red[tid] = loc; __syncthreads();
#pragma unroll
        for (int o = 128; o > 0; o >>= 1) {
            if (tid < o) red[tid] += red[tid + o];
            __syncthreads();
        }
        if (tid == 0) atomicAdd(&g_acc[slot], red[0]);
    }
}

// ===== bf16x3 two-class MMA core (shared by precompute + mainloop) =====
struct MmaAcc { float H[2][8][4]; float R[2][8][4]; };

__device__ __forceinline__ void mma_core(
    MmaAcc& A_, const __nv_bfloat16* const* ops, int rowA0, int colB0, int K,
    uint32_t sb, int tid, uint32_t aLane, uint32_t bLane)
{
    const int lrow = tid >> 3, lpart = tid & 7;
    auto load_chunk = [&](int c, int buf) {
        uint32_t bo = sb + (uint32_t)buf * BUFBYTES + (uint32_t)lpart * 16u;
        int kc = c * 64 + lpart * 8;
#pragma unroll
        for (int op = 0; op < 6; op++) {
            const __nv_bfloat16* sp = ops[op];
            const int row0 = (op < 3) ? rowA0 : colB0;
            uint32_t so = bo + (uint32_t)op * OPBYTES;
#pragma unroll
            for (int q = 0; q < 4; q++) {
                int row = lrow + q * 32;
                cpasync16(so + (uint32_t)row * 144u, sp + (size_t)(row0 + row) * K + kc);
            }
        }
    };

    const int nch = K >> 6;
    load_chunk(0, 0); CP_COMMIT();
    for (int c = 0; c < nch; c++) {
        if (c + 1 < nch) { load_chunk(c + 1, (c + 1) & 1); CP_COMMIT(); CP_WAIT1(); }
        else             { CP_WAIT0(); }
        __syncthreads();
        uint32_t bo = sb + (uint32_t)(c & 1) * BUFBYTES;
#pragma unroll
        for (int kk = 0; kk < 4; kk++) {
            uint32_t kb = (uint32_t)kk * 32u;
            uint32_t ah[2][4], am[2][4], al[2][4];
            ldsm4(ah[0], bo + aLane + kb);
            ldsm4(ah[1], bo + aLane + kb + 16u * 144u);
            ldsm4(am[0], bo + OPBYTES + aLane + kb);
            ldsm4(am[1], bo + OPBYTES + aLane + kb + 16u * 144u);
            ldsm4(al[0], bo + 2u * OPBYTES + aLane + kb);
            ldsm4(al[1], bo + 2u * OPBYTES + aLane + kb + 16u * 144u);
#pragma unroll
            for (int p = 0; p < 4; p++) {
                uint32_t bh[4], bm[4], bl[4];
                uint32_t pb = bLane + kb + (uint32_t)p * (16u * 144u);
                ldsm4(bh, bo + 3u * OPBYTES + pb);
                ldsm4(bm, bo + 4u * OPBYTES + pb);
                ldsm4(bl, bo + 5u * OPBYTES + pb);
#pragma unroll
                for (int s = 0; s < 2; s++) {
                    mma_bf16(A_.H[s][2*p],   ah[s], bh[0], bh[1]);
                    mma_bf16(A_.H[s][2*p+1], ah[s], bh[2], bh[3]);
                    mma_bf16(A_.R[s][2*p],   ah[s], bm[0], bm[1]);
                    mma_bf16(A_.R[s][2*p+1], ah[s], bm[2], bm[3]);
                    mma_bf16(A_.R[s][2*p],   am[s], bh[0], bh[1]);
                    mma_bf16(A_.R[s][2*p+1], am[s], bh[2], bh[3]);
                    mma_bf16(A_.R[s][2*p],   ah[s], bl[0], bl[1]);
                    mma_bf16(A_.R[s][2*p+1], ah[s], bl[2], bl[3]);
                    mma_bf16(A_.R[s][2*p],   al[s], bh[0], bh[1]);
                    mma_bf16(A_.R[s][2*p+1], al[s], bh[2], bh[3]);
                    mma_bf16(A_.R[s][2*p],   am[s], bm[0], bm[1]);
                    mma_bf16(A_.R[s][2*p+1], am[s], bm[2], bm[3]);
                    mma_bf16(A_.R[s][2*p],   am[s], bl[0], bl[1]);
                    mma_bf16(A_.R[s][2*p+1], am[s], bl[2], bl[3]);
                    mma_bf16(A_.R[s][2*p],   al[s], bm[0], bm[1]);
                    mma_bf16(A_.R[s][2*p+1], al[s], bm[2], bm[3]);
                }
            }
        }
        __syncthreads();
    }
}

// ===== precompute MMA GEMM (EPI 0 store, 1 store+fro) — L-path only (DDt, squarings) =====
template<int EPI>
__global__ void __launch_bounds__(256) k_mmaPre(
    const __nv_bfloat16* __restrict__ Ah, const __nv_bfloat16* __restrict__ Am,
    const __nv_bfloat16* __restrict__ Al,
    const __nv_bfloat16* __restrict__ Bh, const __nv_bfloat16* __restrict__ Bm,
    const __nv_bfloat16* __restrict__ Bl,
    float* __restrict__ Cout, int K, int ldC, int slot)
{
    extern __shared__ char dsm[];
    const int tid = threadIdx.x, wid = tid >> 5, lane = tid & 31;
    const int warpM = wid & 3, warpN = wid >> 2;
    const int rowA0 = blockIdx.y * 128;
    const int colB0 = blockIdx.x * 128;
    uint32_t raw = smem_to_u32(dsm);
    const uint32_t sb = (raw + 1023u) & ~1023u;

    MmaAcc A_;
#pragma unroll
    for (int s = 0; s < 2; s++)
#pragma unroll
        for (int t = 0; t < 8; t++)
#pragma unroll
            for (int r = 0; r < 4; r++) { A_.H[s][t][r] = 0.f; A_.R[s][t][r] = 0.f; }

    const __nv_bfloat16* ops[6] = {Ah, Am, Al, Bh, Bm, Bl};
    const uint32_t aLane = (uint32_t)((warpM * 32 + (lane & 15)) * 144 + (lane >> 4) * 16);
    const uint32_t bLane = (uint32_t)((warpN * 64 + (lane & 7) + ((lane >> 4) << 3)) * 144
                                      + ((lane >> 3) & 1) * 16);
    mma_core(A_, ops, rowA0, colB0, K, sb, tid, aLane, bLane);

    float loc = 0.f;
    const int mBase = rowA0 + warpM * 32 + (lane >> 2);
    const int nBase = colB0 + warpN * 64 + (lane & 3) * 2;
#pragma unroll
    for (int s = 0; s < 2; s++) {
#pragma unroll
        for (int t = 0; t < 8; t++) {
            const int n = nBase + t * 8;
#pragma unroll
            for (int h = 0; h < 2; h++) {
                const int m = mBase + s * 16 + h * 8;
                float v0 = A_.H[s][t][h * 2]     + A_.R[s][t][h * 2];
                float v1 = A_.H[s][t][h * 2 + 1] + A_.R[s][t][h * 2 + 1];
                *reinterpret_cast<float2*>(&Cout[(size_t)m * ldC + n]) = make_float2(v0, v1);
                if (EPI == 1) loc += v0 * v0 + v1 * v1;
            }
        }
    }
    if (EPI == 1) {
#pragma unroll
        for (int o = 16; o > 0; o >>= 1) loc += __shfl_down_sync(0xffffffffu, loc, o);
        if (lane == 0) atomicAdd(&g_acc[slot], loc);
    }
}

// ===== mainloop MMA (bitwise-identical arithmetic to R15) + done-guard + fused scalar =====
__global__ void __launch_bounds__(256) k_mma2(
    const __nv_bfloat16* __restrict__ Ah, const __nv_bfloat16* __restrict__ Am,
    const __nv_bfloat16* __restrict__ Al,
    const __nv_bfloat16* __restrict__ Bh, const __nv_bfloat16* __restrict__ Bm,
    const __nv_bfloat16* __restrict__ Bl,
    float* __restrict__ Cout, int K, int ldC, int phase,
    const float* __restrict__ DtYT, const float* __restrict__ CpT,
    const float* __restrict__ CcT,  const float* __restrict__ lamT)
{
    extern __shared__ char dsm[];
    const int tid = threadIdx.x, wid = tid >> 5, lane = tid & 31;

    if (g_done) {   // converged: skip work, keep counter protocol
        if (tid == 0) {
            int old = atomicAdd(&g_ctr, 1);
            if (old == (int)(gridDim.x * gridDim.y) - 1) { g_ctr = 0; g_do = 0; g_norm2 = 0.f; }
        }
        return;
    }

    const int warpM = wid & 3, warpN = wid >> 2;
    const int rowA0 = blockIdx.y * 128;
    const int colB0 = blockIdx.x * 128;
    uint32_t raw = smem_to_u32(dsm);
    const uint32_t sb = (raw + 1023u) & ~1023u;

    MmaAcc A_;
#pragma unroll
    for (int s = 0; s < 2; s++)
#pragma unroll
        for (int t = 0; t < 8; t++)
#pragma unroll
            for (int r = 0; r < 4; r++) { A_.H[s][t][r] = 0.f; A_.R[s][t][r] = 0.f; }

    const __nv_bfloat16* ops[6] = {Ah, Am, Al, Bh, Bm, Bl};
    const uint32_t aLane = (uint32_t)((warpM * 32 + (lane & 15)) * 144 + (lane >> 4) * 16);
    const uint32_t bLane = (uint32_t)((warpN * 64 + (lane & 7) + ((lane >> 4) << 3)) * 144
                                      + ((lane >> 3) & 1) * 16);
    mma_core(A_, ops, rowA0, colB0, K, sb, tid, aLane, bLane);

    float loc = 0.f;
    const float Lv   = g_L;
    const float tau1 = Lv * 0.1f;
    const int mBase = rowA0 + warpM * 32 + (lane >> 2);
    const int nBase = colB0 + warpN * 64 + (lane & 3) * 2;
#pragma unroll
    for (int s = 0; s < 2; s++) {
#pragma unroll
        for (int t = 0; t < 8; t++) {
            const int n = nBase + t * 8;
#pragma unroll
            for (int h = 0; h < 2; h++) {
                const int m = mBase + s * 16 + h * 8;
                float v0 = A_.H[s][t][h * 2]     + A_.R[s][t][h * 2];
                float v1 = A_.H[s][t][h * 2 + 1] + A_.R[s][t][h * 2 + 1];
                size_t idx = (size_t)m * ldC + n;
                float2 dty = *reinterpret_cast<const float2*>(&DtYT[idx]);
                float2 cp  = *reinterpret_cast<const float2*>(&CpT[idx]);
                float2 cc  = *reinterpret_cast<const float2*>(&CcT[idx]);
                float ta0, ta1;
                if (phase == 1) { ta0 = ta1 = tau1; }
                else {
                    float2 lm = *reinterpret_cast<const float2*>(&lamT[idx]);
                    ta0 = Lv * lm.x; ta1 = Lv * lm.y;
                }
                float w0 = cp.x - Lv * (v0 - dty.x);
                float w1 = cp.y - Lv * (v1 - dty.y);
                float c0 = copysignf(fmaxf(fabsf(w0) - ta0, 0.f), w0);
                float c1 = copysignf(fmaxf(fabsf(w1) - ta1, 0.f), w1);
                float d0 = c0 - cc.x, d1 = c1 - cc.y;
                loc += d0 * d0 + d1 * d1;
                *reinterpret_cast<float2*>(&Cout[idx]) = make_float2(c0, c1);
            }
        }
    }
#pragma unroll
    for (int o = 16; o > 0; o >>= 1) loc += __shfl_down_sync(0xffffffffu, loc, o);
    if (lane == 0) atomicAdd(&g_norm2, loc);

    __syncthreads();
    if (tid == 0) {
        __threadfence();
        int old = atomicAdd(&g_ctr, 1);
        if (old == (int)(gridDim.x * gridDim.y) - 1) {
            g_ctr = 0;
            float n2 = atomicAdd(&g_norm2, 0.f);
            int small = (n2 < 1e-12f) ? 1 : 0;
            int go = (!g_done && !small) ? 1 : 0;
            g_do = go;
            if (small) g_done = 1;
            if (go) {
                float t  = g_t;
                float tn = 0.5f * (1.f + sqrtf(1.f + 4.f * t * t));
                g_tconst = (t - 1.f) / tn;
                g_t = tn;
            }
            g_norm2 = 0.f;
        }
    }
}

// ================= host =================
static float* sym(const void* s) {
    void* p = nullptr;
    cudaGetSymbolAddress(&p, s);
    return (float*)p;
}
static __nv_bfloat16* symb(const void* s) {
    void* p = nullptr;
    cudaGetSymbolAddress(&p, s);
    return (__nv_bfloat16*)p;
}

extern "C" void kernel_launch(void* const* d_in, const int* in_sizes, int n_in,
                              void* d_out, int out_size) {
    const float* Y = (const float*)d_in[0];
    const float* D = (const float*)d_in[1];
    if (n_in >= 2 && in_sizes[0] == NP * TT && in_sizes[1] == BB * TT * JJ) {
        const float* tmp = Y; Y = D; D = tmp;
    }
    float* out = (float*)d_out;

    float* pDt   = sym(g_Dt);
    float* pDtD  = sym(g_DtD);   float* pDDt = sym(g_DDt);
    float* pB1   = sym(g_B1);    float* pB2  = sym(g_B2);
    float* pDtY  = sym(g_DtY);   float* pDtYT = sym(g_DtYT);
    float* pCcT  = sym(g_CcT);   float* pCpT = sym(g_CpT);  float* pCnT = sym(g_CnT);
    float* pLamT = sym(g_lamT);
    float* pX    = sym(g_x);     float* pYv  = sym(g_y);
    __nv_bfloat16 *pDh = symb(g_Dh),     *pDm = symb(g_Dm),     *pDl = symb(g_Dl);
    __nv_bfloat16 *pB1h = symb(g_B1h),   *pB1m = symb(g_B1m),   *pB1l = symb(g_B1l);
    __nv_bfloat16 *pDtDh = symb(g_DtDh), *pDtDm = symb(g_DtDm), *pDtDl = symb(g_DtDl);
    __nv_bfloat16 *pCpTh = symb(g_CpTh), *pCpTm = symb(g_CpTm), *pCpTl = symb(g_CpTl);

    cudaFuncSetAttribute(k_mma2, cudaFuncAttributeMaxDynamicSharedMemorySize, SMEMSZ);
    cudaFuncSetAttribute(k_mmaPre<0>, cudaFuncAttributeMaxDynamicSharedMemorySize, SMEMSZ);
    cudaFuncSetAttribute(k_mmaPre<1>, cudaFuncAttributeMaxDynamicSharedMemorySize, SMEMSZ);

    k_init<<<2048, 256>>>();
    k_transpose<<<dim3(NP/32, TT/32), dim3(32, 8)>>>(D);

    // sensitive precompute: fp32 (R15 unchanged)
    k_sgemm64<0,0><<<dim3(NP/64, NP/64), 256>>>(pDt, D, pDtD, NP, NP, TT, 0);
    k_sgemm64<1,0><<<dim3(BJ/64, NP/64), 256>>>(pDt, Y, pDtY, NP, BJ, TT, 0);
    k_transposeG<<<dim3(BJ/32, NP/32), dim3(32, 8)>>>(pDtY, pDtYT, NP, BJ);
    k_split3<<<4096, 256>>>(pDtD, pDtDh, pDtDm, pDtDl, NP*NP);

    // L-path precompute: two-class MMA (insensitive per R9)
    k_split3<<<2048, 256>>>(D, pDh, pDm, pDl, TT*NP);
    // DDt[s,t] = sum_p D[s,p]D[t,p]  M=N=1024, K=2048
    k_mmaPre<0><<<dim3(TT/128, TT/128), 256, SMEMSZ>>>(pDh, pDm, pDl, pDh, pDm, pDl,
                                                       pDDt, NP, TT, 0);
    k_zero<<<1,1>>>(0);
    k_fro<<<256,256>>>(pDDt, TT*TT, 0);
    k_scale_split3<<<1024,256>>>(pDDt, pB1, pB1h, pB1m, pB1l, TT*TT, 0);
    for (int s = 0; s < NSQ; s++) {
        k_zero<<<1,1>>>(1);
        k_mmaPre<1><<<dim3(TT/128, TT/128), 256, SMEMSZ>>>(pB1h, pB1m, pB1l,
                                                           pB1h, pB1m, pB1l,
                                                           pB2, TT, TT, 1);
        k_scale_split3<<<1024,256>>>(pB2, pB1, pB1h, pB1m, pB1l, TT*TT, 1);
    }
    for (int s = 0; s < NPOW; s++) {
        k_zero<<<1,1>>>(2);
        k_matvec<<<TT/8, 256>>>(pB1, pX, pYv, 2, 0);
        k_normalize<<<1, 1024>>>(2);
    }
    k_zero<<<1,1>>>(10);
    k_zero<<<1,1>>>(11);
    k_matvec<<<TT/8, 256>>>(pDDt, pX, pYv, 10, 1);
    k_setL<<<1,1>>>();

    // FISTA mainloop (unchanged arithmetic)
    for (int it = 0; it < 25; it++) {
        k_mma2<<<dim3(NP/128, BJ/128), 256, SMEMSZ>>>(pCpTh, pCpTm, pCpTl,
                                                      pDtDh, pDtDm, pDtDl, pCnT,
                                                      NP, NP, 1, pDtYT, pCpT, pCcT, pLamT);
        k_commit<<<2048, 256>>>();
    }
    k_reweight<<<BJ, 256>>>();
    k_phase_reset<<<1,1>>>();
    for (int it = 0; it < 25; it++) {
        k_mma2<<<dim3(NP/128, BJ/128), 256, SMEMSZ>>>(pCpTh, pCpTm, pCpTl,
                                                      pDtDh, pDtDm, pDtDl, pCnT,
                                                      NP, NP, 2, pDtYT, pCpT, pCcT, pLamT);
        k_commit<<<2048, 256>>>();
    }

    k_output<<<2048, 256>>>(out);
}

// round 17
// speedup vs baseline: 1.0386x; 1.0386x over previous
#include <cuda_runtime.h>
#include <cuda_bf16.h>
#include <math.h>
#include <stdint.h>

#define NP 2048
#define TT 1024
#define BB 16
#define JJ 64
#define BJ 1024
#define NSQ 7
#define NPOW 6

// MMA smem: 6 operand tiles [128 rows x 64 bf16] pitch 144B, double buffered
#define OPBYTES 18432u
#define BUFBYTES (6u * OPBYTES)        // 110592
#define SMEMSZ (2 * 110592 + 1024)     // 222208, 1 CTA/SM

// ================= PTX helpers =================
__device__ __forceinline__ uint32_t smem_to_u32(const void* p) {
    uint32_t a;
    asm("{ .reg .u64 t; cvta.to.shared.u64 t, %1; cvt.u32.u64 %0, t; }" : "=r"(a) : "l"(p));
    return a;
}
__device__ __forceinline__ void ldsm4(uint32_t* r, uint32_t addr) {
    asm volatile("ldmatrix.sync.aligned.m8n8.x4.shared.b16 {%0,%1,%2,%3}, [%4];"
                 : "=r"(r[0]), "=r"(r[1]), "=r"(r[2]), "=r"(r[3]) : "r"(addr));
}
__device__ __forceinline__ void mma_bf16(float* d, const uint32_t* a, uint32_t b0, uint32_t b1) {
    asm volatile(
        "mma.sync.aligned.m16n8k16.row.col.f32.bf16.bf16.f32 "
        "{%0,%1,%2,%3}, {%4,%5,%6,%7}, {%8,%9}, {%0,%1,%2,%3};"
        : "+f"(d[0]), "+f"(d[1]), "+f"(d[2]), "+f"(d[3])
        : "r"(a[0]), "r"(a[1]), "r"(a[2]), "r"(a[3]), "r"(b0), "r"(b1));
}
__device__ __forceinline__ void cpasync16(uint32_t dst, const void* src) {
    asm volatile("cp.async.cg.shared.global [%0], [%1], 16;" :: "r"(dst), "l"(src));
}
#define CP_COMMIT() asm volatile("cp.async.commit_group;" ::: "memory")
#define CP_WAIT0()  asm volatile("cp.async.wait_group 0;" ::: "memory")
#define CP_WAIT1()  asm volatile("cp.async.wait_group 1;" ::: "memory")

// ================= device scratch =================
__device__ __align__(16) float g_Dt  [NP*TT];
__device__ __align__(16) float g_DtD [NP*NP];
__device__ __align__(16) float g_DDt [TT*TT];
__device__ __align__(16) float g_B1  [TT*TT];
__device__ __align__(16) float g_B2  [TT*TT];
__device__ __align__(16) float g_DtY [NP*BJ];
__device__ __align__(16) float g_DtYT[BJ*NP];
__device__ __align__(16) float g_CcT [BJ*NP];
__device__ __align__(16) float g_CpT [BJ*NP];
__device__ __align__(16) float g_lamT[BJ*NP];
__device__ __align__(16) __nv_bfloat16 g_DtDh[NP*NP], g_DtDm[NP*NP], g_DtDl[NP*NP];
// ping-pong Cp split buffers (A-operand is read cross-CTA while next is written)
__device__ __align__(16) __nv_bfloat16 g_CpTh0[BJ*NP], g_CpTm0[BJ*NP], g_CpTl0[BJ*NP];
__device__ __align__(16) __nv_bfloat16 g_CpTh1[BJ*NP], g_CpTm1[BJ*NP], g_CpTl1[BJ*NP];
__device__ float g_x[TT], g_y[TT];
__device__ float g_acc[16];
__device__ float g_L;

// ================= small kernels =================
__global__ void k_init() {
    int idx = blockIdx.x * blockDim.x + threadIdx.x;
    int stride = gridDim.x * blockDim.x;
    __nv_bfloat16 z = __float2bfloat16(0.f);
    for (int i = idx; i < BJ*NP; i += stride) {
        g_CcT[i] = 0.f; g_CpT[i] = 0.f;
        g_CpTh0[i] = z; g_CpTm0[i] = z; g_CpTl0[i] = z;
    }
    if (idx < TT) {
        unsigned h = (unsigned)idx * 2654435761u;
        g_x[idx] = 0.5f + (float)(h >> 20) * (1.0f / 4096.0f);
    }
    if (idx < 16) g_acc[idx] = 0.f;
    if (idx == 0) g_L = 0.f;
}
__global__ void k_zero(int s) { g_acc[s] = 0.f; }

__global__ void k_transpose(const float* __restrict__ D) {   // D[TT,NP] -> Dt[NP,TT]
    __shared__ float tile[32][33];
    int p0 = blockIdx.x * 32, t0 = blockIdx.y * 32;
    int tx = threadIdx.x, ty = threadIdx.y;
#pragma unroll
    for (int r = 0; r < 32; r += 8)
        tile[ty + r][tx] = D[(size_t)(t0 + ty + r) * NP + p0 + tx];
    __syncthreads();
#pragma unroll
    for (int r = 0; r < 32; r += 8)
        g_Dt[(size_t)(p0 + ty + r) * TT + t0 + tx] = tile[tx][ty + r];
}
__global__ void k_transposeG(const float* __restrict__ src, float* __restrict__ dst,
                             int R, int C) {
    __shared__ float tile[32][33];
    int c0 = blockIdx.x * 32, r0 = blockIdx.y * 32;
    int tx = threadIdx.x, ty = threadIdx.y;
#pragma unroll
    for (int r = 0; r < 32; r += 8)
        tile[ty + r][tx] = src[(size_t)(r0 + ty + r) * C + c0 + tx];
    __syncthreads();
#pragma unroll
    for (int r = 0; r < 32; r += 8)
        dst[(size_t)(c0 + ty + r) * R + r0 + tx] = tile[tx][ty + r];
}

__device__ __forceinline__ void split3(float v, __nv_bfloat16& h, __nv_bfloat16& m,
                                       __nv_bfloat16& l) {
    __nv_bfloat16 hb = __float2bfloat16(v);
    float r1 = v - __bfloat162float(hb);
    __nv_bfloat16 mb = __float2bfloat16(r1);
    float r2 = r1 - __bfloat162float(mb);
    h = hb; m = mb; l = __float2bfloat16(r2);
}
__global__ void k_split3(const float* __restrict__ src, __nv_bfloat16* __restrict__ h,
                         __nv_bfloat16* __restrict__ m, __nv_bfloat16* __restrict__ l, int n) {
    int idx = blockIdx.x * blockDim.x + threadIdx.x;
    int stride = gridDim.x * blockDim.x;
    for (int i = idx; i < n; i += stride) split3(src[i], h[i], m[i], l[i]);
}

__global__ void k_fro(const float* __restrict__ A, int n, int slot) {
    __shared__ float red[256];
    float s = 0.f;
    for (int i = blockIdx.x * blockDim.x + threadIdx.x; i < n; i += gridDim.x * blockDim.x) {
        float v = A[i]; s += v * v;
    }
    red[threadIdx.x] = s; __syncthreads();
    for (int o = 128; o > 0; o >>= 1) {
        if (threadIdx.x < o) red[threadIdx.x] += red[threadIdx.x + o];
        __syncthreads();
    }
    if (threadIdx.x == 0) atomicAdd(&g_acc[slot], red[0]);
}
__global__ void k_scale(const float* __restrict__ src, float* __restrict__ dst, int n, int slot) {
    float inv = rsqrtf(g_acc[slot]);
    for (int i = blockIdx.x * blockDim.x + threadIdx.x; i < n; i += gridDim.x * blockDim.x)
        dst[i] = src[i] * inv;
}
__global__ void k_matvec(const float* __restrict__ A, const float* __restrict__ xin,
                         float* __restrict__ yout, int slot, int mode) {
    int row  = blockIdx.x * 8 + (threadIdx.x >> 5);
    int lane = threadIdx.x & 31;
    const float* ar = A + (size_t)row * TT;
    float s = 0.f;
    for (int k = lane; k < TT; k += 32) s += ar[k] * xin[k];
#pragma unroll
    for (int o = 16; o > 0; o >>= 1) s += __shfl_down_sync(0xffffffffu, s, o);
    if (lane == 0) {
        yout[row] = s;
        if (mode == 0) atomicAdd(&g_acc[slot], s * s);
        else { float xv = xin[row]; atomicAdd(&g_acc[10], xv * s); atomicAdd(&g_acc[11], xv * xv); }
    }
}
__global__ void k_normalize(int slot) {
    int i = threadIdx.x;
    float inv = rsqrtf(g_acc[slot]);
    g_x[i] = g_y[i] * inv;
}
__global__ void k_setL() { g_L = g_acc[11] / g_acc[10]; }

__global__ void k_reweight() {
    __shared__ float red[256];
    int c = blockIdx.x;
    const float* row = g_CcT + (size_t)c * NP;
    float s = 0.f;
    for (int p = threadIdx.x; p < NP; p += 256) {
        float w = 1.f / (fabsf(row[p]) + 1e-10f);
        s += w * w;
    }
    red[threadIdx.x] = s; __syncthreads();
    for (int o = 128; o > 0; o >>= 1) {
        if (threadIdx.x < o) red[threadIdx.x] += red[threadIdx.x + o];
        __syncthreads();
    }
    float inv = rsqrtf(red[0]);
    for (int p = threadIdx.x; p < NP; p += 256) {
        float w = 1.f / (fabsf(row[p]) + 1e-10f);
        g_lamT[(size_t)c * NP + p] = 0.1f * 2048.f * w * inv;
    }
}
__global__ void k_output(float* __restrict__ out) {
    int idx = blockIdx.x * blockDim.x + threadIdx.x;
    int stride = gridDim.x * blockDim.x;
    for (int i = idx; i < BB * NP * JJ; i += stride) {
        int j = i & 63;
        int p = (i >> 6) & (NP - 1);
        int b = i >> 17;
        out[i] = g_CcT[(size_t)(b * JJ + j) * NP + p];
    }
}

// ============== fp32 SGEMM, 64x64 tile (R15, unchanged) ==============
template<int BMAP, int EPI>
__global__ void __launch_bounds__(256) k_sgemm64(const float* __restrict__ A,
                                                 const float* __restrict__ B,
                                                 float* __restrict__ C,
                                                 int M, int N, int K, int slot)
{
    __shared__ float As[2][16][68];
    __shared__ float Bs[2][16][64];
    __shared__ float red[256];
    const int tid   = threadIdx.x;
    const int rowA0 = blockIdx.y * 64;
    const int colB0 = blockIdx.x * 64;
    const int aRow = tid >> 2,  aCol = (tid & 3) * 4;
    const int bRow = tid >> 4,  bCol = (tid & 15) * 4;
    const int tr = tid >> 4,    tc = tid & 15;
    const float* Ag = A + (size_t)(rowA0 + aRow) * K + aCol;

    float acc[4][4];
#pragma unroll
    for (int i = 0; i < 4; i++)
#pragma unroll
        for (int j = 0; j < 4; j++) acc[i][j] = 0.f;

    float4 a0, b0;
    {
        a0 = *reinterpret_cast<const float4*>(Ag);
        if (BMAP == 0) {
            b0 = *reinterpret_cast<const float4*>(B + (size_t)(bRow) * N + colB0 + bCol);
        } else {
            int c = colB0 + bCol;
            const float* Bb = B + (size_t)(c >> 6) * (TT * JJ) + (c & 63);
            b0 = *reinterpret_cast<const float4*>(Bb + (size_t)(bRow) * JJ);
        }
        As[0][aCol + 0][aRow] = a0.x; As[0][aCol + 1][aRow] = a0.y;
        As[0][aCol + 2][aRow] = a0.z; As[0][aCol + 3][aRow] = a0.w;
        *reinterpret_cast<float4*>(&Bs[0][bRow][bCol]) = b0;
    }
    __syncthreads();

    int buf = 0;
    for (int k0 = 16; k0 <= K; k0 += 16) {
        if (k0 < K) {
            a0 = *reinterpret_cast<const float4*>(Ag + k0);
            if (BMAP == 0) {
                b0 = *reinterpret_cast<const float4*>(B + (size_t)(k0 + bRow) * N + colB0 + bCol);
            } else {
                int c = colB0 + bCol;
                const float* Bb = B + (size_t)(c >> 6) * (TT * JJ) + (c & 63);
                b0 = *reinterpret_cast<const float4*>(Bb + (size_t)(k0 + bRow) * JJ);
            }
        }
#pragma unroll
        for (int kk = 0; kk < 16; kk++) {
            float4 m0 = *reinterpret_cast<const float4*>(&As[buf][kk][tr * 4]);
            float4 n0 = *reinterpret_cast<const float4*>(&Bs[buf][kk][tc * 4]);
            float rm[4] = {m0.x, m0.y, m0.z, m0.w};
            float rn[4] = {n0.x, n0.y, n0.z, n0.w};
#pragma unroll
            for (int i = 0; i < 4; i++)
#pragma unroll
                for (int j = 0; j < 4; j++) acc[i][j] += rm[i] * rn[j];
        }
        if (k0 < K) {
            int nb = buf ^ 1;
            As[nb][aCol + 0][aRow] = a0.x; As[nb][aCol + 1][aRow] = a0.y;
            As[nb][aCol + 2][aRow] = a0.z; As[nb][aCol + 3][aRow] = a0.w;
            *reinterpret_cast<float4*>(&Bs[nb][bRow][bCol]) = b0;
            __syncthreads();
            buf = nb;
        }
    }

    float loc = 0.f;
#pragma unroll
    for (int i = 0; i < 4; i++) {
        size_t base = (size_t)(rowA0 + tr * 4 + i) * N + colB0 + tc * 4;
        float4 r;
        r.x = acc[i][0]; r.y = acc[i][1]; r.z = acc[i][2]; r.w = acc[i][3];
        *reinterpret_cast<float4*>(&C[base]) = r;
        if (EPI == 1) loc += r.x * r.x + r.y * r.y + r.z * r.z + r.w * r.w;
    }
    if (EPI == 1) {
        red[tid] = loc; __syncthreads();
#pragma unroll
        for (int o = 128; o > 0; o >>= 1) {
            if (tid < o) red[tid] += red[tid + o];
            __syncthreads();
        }
        if (tid == 0) atomicAdd(&g_acc[slot], red[0]);
    }
}

// ===== mainloop: bf16x3 8-product two-class HMMA GEMM (arithmetic = R15), fused commit =====
// Reads Cp split bufs (Ah/Am/Al) + DtD (Bh/Bm/Bl); epilogue computes cn, then
// cp' = cn + tc*(cn-cc); writes CcT=cn, CpT=cp', split3(cp') -> write bufs (Wh/Wm/Wl).
// t-sequence is data-independent (freeze never fires; if it did, deltas < TOL=1e-6).
__global__ void __launch_bounds__(256) k_mma2(
    const __nv_bfloat16* __restrict__ Ah, const __nv_bfloat16* __restrict__ Am,
    const __nv_bfloat16* __restrict__ Al,
    const __nv_bfloat16* __restrict__ Bh, const __nv_bfloat16* __restrict__ Bm,
    const __nv_bfloat16* __restrict__ Bl,
    __nv_bfloat16* __restrict__ Wh, __nv_bfloat16* __restrict__ Wm,
    __nv_bfloat16* __restrict__ Wl,
    int K, int ldC, int phase, float tcst,
    const float* __restrict__ DtYT, float* __restrict__ CpT,
    float* __restrict__ CcT, const float* __restrict__ lamT)
{
    extern __shared__ char dsm[];
    const int tid = threadIdx.x, wid = tid >> 5, lane = tid & 31;
    const int warpM = wid & 3, warpN = wid >> 2;
    const int rowA0 = blockIdx.y * 128;
    const int colB0 = blockIdx.x * 128;
    uint32_t raw = smem_to_u32(dsm);
    const uint32_t sb = (raw + 1023u) & ~1023u;

    float accH[2][8][4], accR[2][8][4];
#pragma unroll
    for (int s = 0; s < 2; s++)
#pragma unroll
        for (int t = 0; t < 8; t++)
#pragma unroll
            for (int r = 0; r < 4; r++) { accH[s][t][r] = 0.f; accR[s][t][r] = 0.f; }

    const __nv_bfloat16* ops[6] = {Ah, Am, Al, Bh, Bm, Bl};
    const int lrow = tid >> 3, lpart = tid & 7;
    auto load_chunk = [&](int c, int buf) {
        uint32_t bo = sb + (uint32_t)buf * BUFBYTES + (uint32_t)lpart * 16u;
        int kc = c * 64 + lpart * 8;
#pragma unroll
        for (int op = 0; op < 6; op++) {
            const __nv_bfloat16* sp = ops[op];
            const int row0 = (op < 3) ? rowA0 : colB0;
            uint32_t so = bo + (uint32_t)op * OPBYTES;
#pragma unroll
            for (int q = 0; q < 4; q++) {
                int row = lrow + q * 32;
                cpasync16(so + (uint32_t)row * 144u, sp + (size_t)(row0 + row) * K + kc);
            }
        }
    };

    const uint32_t aLane = (uint32_t)((warpM * 32 + (lane & 15)) * 144 + (lane >> 4) * 16);
    const uint32_t bLane = (uint32_t)((warpN * 64 + (lane & 7) + ((lane >> 4) << 3)) * 144
                                      + ((lane >> 3) & 1) * 16);

    const int nch = K >> 6;
    load_chunk(0, 0); CP_COMMIT();
    for (int c = 0; c < nch; c++) {
        if (c + 1 < nch) { load_chunk(c + 1, (c + 1) & 1); CP_COMMIT(); CP_WAIT1(); }
        else             { CP_WAIT0(); }
        __syncthreads();
        uint32_t bo = sb + (uint32_t)(c & 1) * BUFBYTES;
#pragma unroll
        for (int kk = 0; kk < 4; kk++) {
            uint32_t kb = (uint32_t)kk * 32u;
            uint32_t ah[2][4], am[2][4], al[2][4];
            ldsm4(ah[0], bo + aLane + kb);
            ldsm4(ah[1], bo + aLane + kb + 16u * 144u);
            ldsm4(am[0], bo + OPBYTES + aLane + kb);
            ldsm4(am[1], bo + OPBYTES + aLane + kb + 16u * 144u);
            ldsm4(al[0], bo + 2u * OPBYTES + aLane + kb);
            ldsm4(al[1], bo + 2u * OPBYTES + aLane + kb + 16u * 144u);
#pragma unroll
            for (int p = 0; p < 4; p++) {
                uint32_t bh[4], bm[4], bl[4];
                uint32_t pb = bLane + kb + (uint32_t)p * (16u * 144u);
                ldsm4(bh, bo + 3u * OPBYTES + pb);
                ldsm4(bm, bo + 4u * OPBYTES + pb);
                ldsm4(bl, bo + 5u * OPBYTES + pb);
#pragma unroll
                for (int s = 0; s < 2; s++) {
                    mma_bf16(accH[s][2*p],   ah[s], bh[0], bh[1]);
                    mma_bf16(accH[s][2*p+1], ah[s], bh[2], bh[3]);
                    mma_bf16(accR[s][2*p],   ah[s], bm[0], bm[1]);
                    mma_bf16(accR[s][2*p+1], ah[s], bm[2], bm[3]);
                    mma_bf16(accR[s][2*p],   am[s], bh[0], bh[1]);
                    mma_bf16(accR[s][2*p+1], am[s], bh[2], bh[3]);
                    mma_bf16(accR[s][2*p],   ah[s], bl[0], bl[1]);
                    mma_bf16(accR[s][2*p+1], ah[s], bl[2], bl[3]);
                    mma_bf16(accR[s][2*p],   al[s], bh[0], bh[1]);
                    mma_bf16(accR[s][2*p+1], al[s], bh[2], bh[3]);
                    mma_bf16(accR[s][2*p],   am[s], bm[0], bm[1]);
                    mma_bf16(accR[s][2*p+1], am[s], bm[2], bm[3]);
                    mma_bf16(accR[s][2*p],   am[s], bl[0], bl[1]);
                    mma_bf16(accR[s][2*p+1], am[s], bl[2], bl[3]);
                    mma_bf16(accR[s][2*p],   al[s], bm[0], bm[1]);
                    mma_bf16(accR[s][2*p+1], al[s], bm[2], bm[3]);
                }
            }
        }
        __syncthreads();
    }

    const float Lv   = g_L;
    const float tau1 = Lv * 0.1f;
    const int mBase = rowA0 + warpM * 32 + (lane >> 2);
    const int nBase = colB0 + warpN * 64 + (lane & 3) * 2;
#pragma unroll
    for (int s = 0; s < 2; s++) {
#pragma unroll
        for (int t = 0; t < 8; t++) {
            const int n = nBase + t * 8;
#pragma unroll
            for (int h = 0; h < 2; h++) {
                const int m = mBase + s * 16 + h * 8;
                float v0 = accH[s][t][h * 2]     + accR[s][t][h * 2];
                float v1 = accH[s][t][h * 2 + 1] + accR[s][t][h * 2 + 1];
                size_t idx = (size_t)m * ldC + n;
                float2 dty = *reinterpret_cast<const float2*>(&DtYT[idx]);
                float2 cp  = *reinterpret_cast<const float2*>(&CpT[idx]);
                float2 cc  = *reinterpret_cast<const float2*>(&CcT[idx]);
                float ta0, ta1;
                if (phase == 1) { ta0 = ta1 = tau1; }
                else {
                    float2 lm = *reinterpret_cast<const float2*>(&lamT[idx]);
                    ta0 = Lv * lm.x; ta1 = Lv * lm.y;
                }
                float w0 = cp.x - Lv * (v0 - dty.x);
                float w1 = cp.y - Lv * (v1 - dty.y);
                float c0 = copysignf(fmaxf(fabsf(w0) - ta0, 0.f), w0);
                float c1 = copysignf(fmaxf(fabsf(w1) - ta1, 0.f), w1);
                // fused commit: Cp' = Cn + tc*(Cn - Cc); Cc = Cn
                float p0 = c0 + tcst * (c0 - cc.x);
                float p1 = c1 + tcst * (c1 - cc.y);
                *reinterpret_cast<float2*>(&CcT[idx]) = make_float2(c0, c1);
                *reinterpret_cast<float2*>(&CpT[idx]) = make_float2(p0, p1);
                __nv_bfloat16 h0, m0, l0, h1, m1, l1;
                split3(p0, h0, m0, l0);
                split3(p1, h1, m1, l1);
                __nv_bfloat162 hp; hp.x = h0; hp.y = h1;
                __nv_bfloat162 mp; mp.x = m0; mp.y = m1;
                __nv_bfloat162 lp; lp.x = l0; lp.y = l1;
                *reinterpret_cast<__nv_bfloat162*>(&Wh[idx]) = hp;
                *reinterpret_cast<__nv_bfloat162*>(&Wm[idx]) = mp;
                *reinterpret_cast<__nv_bfloat162*>(&Wl[idx]) = lp;
            }
        }
    }
}

// ================= host =================
static float* sym(const void* s) {
    void* p = nullptr;
    cudaGetSymbolAddress(&p, s);
    return (float*)p;
}
static __nv_bfloat16* symb(const void* s) {
    void* p = nullptr;
    cudaGetSymbolAddress(&p, s);
    return (__nv_bfloat16*)p;
}

extern "C" void kernel_launch(void* const* d_in, const int* in_sizes, int n_in,
                              void* d_out, int out_size) {
    const float* Y = (const float*)d_in[0];
    const float* D = (const float*)d_in[1];
    if (n_in >= 2 && in_sizes[0] == NP * TT && in_sizes[1] == BB * TT * JJ) {
        const float* tmp = Y; Y = D; D = tmp;
    }
    float* out = (float*)d_out;

    float* pDt   = sym(g_Dt);
    float* pDtD  = sym(g_DtD);   float* pDDt = sym(g_DDt);
    float* pB1   = sym(g_B1);    float* pB2  = sym(g_B2);
    float* pDtY  = sym(g_DtY);   float* pDtYT = sym(g_DtYT);
    float* pCcT  = sym(g_CcT);   float* pCpT = sym(g_CpT);
    float* pLamT = sym(g_lamT);
    float* pX    = sym(g_x);     float* pYv  = sym(g_y);
    __nv_bfloat16 *pDtDh = symb(g_DtDh), *pDtDm = symb(g_DtDm), *pDtDl = symb(g_DtDl);
    __nv_bfloat16* bufH[2] = { symb(g_CpTh0), symb(g_CpTh1) };
    __nv_bfloat16* bufM[2] = { symb(g_CpTm0), symb(g_CpTm1) };
    __nv_bfloat16* bufL[2] = { symb(g_CpTl0), symb(g_CpTl1) };

    cudaFuncSetAttribute(k_mma2, cudaFuncAttributeMaxDynamicSharedMemorySize, SMEMSZ);

    // deterministic FISTA t-sequence (matches device fp32 formula)
    float tcs[50];
    {
        float t = 1.f;
        for (int k = 0; k < 50; k++) {
            float tn = 0.5f * (1.f + sqrtf(1.f + 4.f * t * t));
            tcs[k] = (t - 1.f) / tn;
            t = tn;
        }
    }

    k_init<<<2048, 256>>>();
    k_transpose<<<dim3(NP/32, TT/32), dim3(32, 8)>>>(D);

    // fp32 precompute (R15 structure, proven fastest)
    k_sgemm64<0,0><<<dim3(NP/64, NP/64), 256>>>(pDt, D, pDtD, NP, NP, TT, 0);
    k_sgemm64<0,0><<<dim3(TT/64, TT/64), 256>>>(D, pDt, pDDt, TT, TT, NP, 0);
    k_sgemm64<1,0><<<dim3(BJ/64, NP/64), 256>>>(pDt, Y, pDtY, NP, BJ, TT, 0);
    k_transposeG<<<dim3(BJ/32, NP/32), dim3(32, 8)>>>(pDtY, pDtYT, NP, BJ);
    k_split3<<<4096, 256>>>(pDtD, pDtDh, pDtDm, pDtDl, NP*NP);

    // spectral norm of DDt (fp32 squarings)
    k_zero<<<1,1>>>(0);
    k_fro<<<256,256>>>(pDDt, TT*TT, 0);
    k_scale<<<256,256>>>(pDDt, pB1, TT*TT, 0);
    for (int s = 0; s < NSQ; s++) {
        k_zero<<<1,1>>>(1);
        k_sgemm64<0,1><<<dim3(TT/64, TT/64), 256>>>(pB1, pB1, pB2, TT, TT, TT, 1);
        k_scale<<<256,256>>>(pB2, pB1, TT*TT, 1);
    }
    for (int s = 0; s < NPOW; s++) {
        k_zero<<<1,1>>>(2);
        k_matvec<<<TT/8, 256>>>(pB1, pX, pYv, 2, 0);
        k_normalize<<<1, 1024>>>(2);
    }
    k_zero<<<1,1>>>(10);
    k_zero<<<1,1>>>(11);
    k_matvec<<<TT/8, 256>>>(pDDt, pX, pYv, 10, 1);
    k_setL<<<1,1>>>();

    // FISTA mainloop: single kernel per iteration, ping-pong Cp split buffers
    int pr = 0;
    for (int it = 0; it < 50; it++) {
        if (it == 25) k_reweight<<<BJ, 256>>>();
        int phase = (it < 25) ? 1 : 2;
        int wr = pr ^ 1;
        k_mma2<<<dim3(NP/128, BJ/128), 256, SMEMSZ>>>(
            bufH[pr], bufM[pr], bufL[pr],
            pDtDh, pDtDm, pDtDl,
            bufH[wr], bufM[wr], bufL[wr],
            NP, NP, phase, tcs[it], pDtYT, pCpT, pCcT, pLamT);
        pr = wr;
    }

    k_output<<<2048, 256>>>(out);
}